// round 1
// baseline (speedup 1.0000x reference)
#include <cuda_runtime.h>
#include <math.h>

#define CC   256
#define HH   40
#define WW   40
#define NROI 64
#define PHB  7
#define PWB  7
#define HW   1600

// scratch (no allocs allowed)
__device__ float g_s[HW];
__device__ float g_mask[HW];

// ---------------------------------------------------------------------------
// Kernel 1: s[p] = sum_c fm[c, p]   (threads over pixels -> coalesced LDGs)
// ---------------------------------------------------------------------------
__global__ void k_sum(const float* __restrict__ fm) {
    int p = blockIdx.x * 128 + threadIdx.x;
    if (p >= HW) return;
    float s = 0.f;
#pragma unroll 8
    for (int c = 0; c < CC; c++) s += fm[c * HW + p];
    g_s[p] = s;
}

// ---------------------------------------------------------------------------
// Kernel 2: smax = max(s); mask_map = 0.5 + 0.4*(s/smax)^4   (single block)
// ---------------------------------------------------------------------------
__global__ void k_mask() {
    __shared__ float red[512];
    int t = threadIdx.x;
    float m = 0.f;  // s >= 0 (fm is uniform [0,1))
    for (int p = t; p < HW; p += 512) m = fmaxf(m, g_s[p]);
    red[t] = m;
    __syncthreads();
    for (int off = 256; off > 0; off >>= 1) {
        if (t < off) red[t] = fmaxf(red[t], red[t + off]);
        __syncthreads();
    }
    float inv = 1.f / red[0];
    for (int p = t; p < HW; p += 512) {
        float x  = g_s[p] * inv;
        float x2 = x * x;
        g_mask[p] = 0.5f + 0.4f * (x2 * x2);
    }
}

// ---------------------------------------------------------------------------
// Kernel 3: fused mask + adaptive max pool.
// grid = (64 ROIs, 4 channel groups), 256 threads (8 warps).
// Lanes map to x (coalesced fm loads); each warp owns 8 channels.
// ---------------------------------------------------------------------------
__global__ void k_pool(const float* __restrict__ fm,
                       const float* __restrict__ rois1,
                       const float* __restrict__ rois2,
                       float* __restrict__ out) {
    __shared__ float smask[HW];
    __shared__ float rbuf[8][40];

    const int n = blockIdx.x;
    const int t = threadIdx.x;
    const int w = t >> 5, l = t & 31;

    const float* a = rois1 + n * 5;
    const float* b = rois2 + n * 5;
    // round-half-even (matches jnp.round), clamp upper side only
    int x1a = min(__float2int_rn(a[1] * 0.0625f), WW - 1);
    int y1a = min(__float2int_rn(a[2] * 0.0625f), HH - 1);
    int x2a = min(__float2int_rn(a[3] * 0.0625f), WW - 1);
    int y2a = min(__float2int_rn(a[4] * 0.0625f), HH - 1);
    int x1b = min(__float2int_rn(b[1] * 0.0625f), WW - 1);
    int y1b = min(__float2int_rn(b[2] * 0.0625f), HH - 1);
    int x2b = min(__float2int_rn(b[3] * 0.0625f), WW - 1);
    int y2b = min(__float2int_rn(b[4] * 0.0625f), HH - 1);

    int ux1 = min(x1a, x1b), uy1 = min(y1a, y1b);
    int ux2 = max(x2a, x2b), uy2 = max(y2a, y2b);

    // effective mask in smem: 1.0 inside either box, else g(saliency)
    for (int p = t; p < HW; p += 256) {
        int y = p / WW, x = p % WW;
        bool inA = (x >= x1a) & (x <= x2a) & (y >= y1a) & (y <= y2a);
        bool inB = (x >= x1b) & (x <= x2b) & (y >= y1b) & (y <= y2b);
        smask[p] = (inA || inB) ? 1.0f : g_mask[p];
    }
    __syncthreads();

    const int hb = uy2 - uy1 + 1;
    const int wb = ux2 - ux1 + 1;
    const int c0 = blockIdx.y * 64;

    for (int ci = 0; ci < 8; ci++) {
        int c = c0 + w + ci * 8;
        const float* base = fm + c * HW;
        for (int ph = 0; ph < PHB; ph++) {
            int ys = uy1 + (ph * hb) / 7;
            int ye = uy1 + ((ph + 1) * hb + 6) / 7;  // ceil, exclusive
            float rr0 = -INFINITY, rr1 = -INFINITY;
            int xg = ux1 + l;
            for (int y = ys; y < ye; y++) {
                const float* row  = base  + y * WW;
                const float* mrow = smask + y * WW;
                if (l < wb)      rr0 = fmaxf(rr0, row[xg]      * mrow[xg]);
                if (l + 32 < wb) rr1 = fmaxf(rr1, row[xg + 32] * mrow[xg + 32]);
            }
            rbuf[w][l] = rr0;
            if (l + 32 < 40) rbuf[w][l + 32] = rr1;
            __syncwarp();
            if (l < PWB) {
                int xs = (l * wb) / 7;
                int xe = ((l + 1) * wb + 6) / 7;
                float m = -INFINITY;
                for (int x = xs; x < xe; x++) m = fmaxf(m, rbuf[w][x]);
                out[((n * CC + c) * PHB + ph) * PWB + l] = m;
            }
            __syncwarp();
        }
    }
}

// ---------------------------------------------------------------------------
extern "C" void kernel_launch(void* const* d_in, const int* in_sizes, int n_in,
                              void* d_out, int out_size) {
    const float* fm = (const float*)d_in[0];
    const float* r1 = (const float*)d_in[1];
    const float* r2 = (const float*)d_in[2];
    float* out = (float*)d_out;

    k_sum<<<(HW + 127) / 128, 128>>>(fm);
    k_mask<<<1, 512>>>();
    k_pool<<<dim3(NROI, 4), 256>>>(fm, r1, r2, out);
}